// round 1
// baseline (speedup 1.0000x reference)
#include <cuda_runtime.h>
#include <math.h>

#define PIX 4096
#define NV 9

// ---------------- scratch (device globals; no allocations allowed) ----------
__device__ float g_x [32ull*64*PIX];   // encoder output x, [t*4+b][c][pix]
__device__ float g_e1[32ull*32*PIX];   // encoder stage 1
__device__ float g_e2[32ull*64*PIX];   // encoder stage 2
__device__ float g_h0[2ull*36*64*PIX]; // ping-pong h0, [p][b*9+v][c][pix]
__device__ float g_h1[2ull*36*64*PIX]; // ping-pong h1
__device__ float g_up[36ull*64*PIX];   // layer-1 conv_u output

__global__ void zero_init_k() {
    // zero parity-0 halves of g_h0/g_h1 (the t=0 read buffers)
    size_t i = (size_t)blockIdx.x * 256 + threadIdx.x;   // exactly 9216*256 threads
    float4 z = make_float4(0.f, 0.f, 0.f, 0.f);
    reinterpret_cast<float4*>(g_h0)[i] = z;
    reinterpret_cast<float4*>(g_h1)[i] = z;
}

// ---------------- encoder conv1: 3->32, 5x5, zero pad 2, BN+ReLU ------------
__global__ void __launch_bounds__(256, 2)
conv1_k(const float* __restrict__ u, const float* __restrict__ wt,
        const float* __restrict__ gm, const float* __restrict__ bt,
        float* __restrict__ out) {
    __shared__ float sIn[400];       // 20x20 tile (halo 2)
    __shared__ float sW[25 * 32];    // [tap][cout]
    int tile = blockIdx.x, e = blockIdx.y;      // e = t*4 + b
    int tstep = e >> 2, bb = e & 3;
    int ty0 = (tile >> 2) << 4, tx0 = (tile & 3) << 4;
    int tid = threadIdx.x, lx = tid & 15, ly = tid >> 4;
    const float* inImg = u + (size_t)(bb * 8 + tstep) * 3 * PIX;  // u[b][t][c]
    float acc[32];
#pragma unroll
    for (int c = 0; c < 32; c++) acc[c] = 0.f;

    for (int k = 0; k < 3; k++) {
        const float* inC = inImg + (size_t)k * PIX;
        for (int i = tid; i < 400; i += 256) {
            int ry = i / 20, rx = i - ry * 20;
            int gy = ty0 + ry - 2, gx = tx0 + rx - 2;
            sIn[i] = (gy >= 0 && gy < 64 && gx >= 0 && gx < 64) ? inC[gy * 64 + gx] : 0.f;
        }
        for (int i = tid; i < 800; i += 256) {
            int c = i / 25, t5 = i - c * 25;
            sW[t5 * 32 + c] = wt[(c * 3 + k) * 25 + t5];
        }
        __syncthreads();
        float n[25];
#pragma unroll
        for (int dy = 0; dy < 5; dy++)
#pragma unroll
            for (int dx = 0; dx < 5; dx++)
                n[dy * 5 + dx] = sIn[(ly + dy) * 20 + lx + dx];
#pragma unroll
        for (int t5 = 0; t5 < 25; t5++) {
            const float4* w4 = (const float4*)(sW + t5 * 32);
            float nb = n[t5];
#pragma unroll
            for (int cc = 0; cc < 8; cc++) {
                float4 w = w4[cc];
                acc[cc * 4 + 0] += nb * w.x;
                acc[cc * 4 + 1] += nb * w.y;
                acc[cc * 4 + 2] += nb * w.z;
                acc[cc * 4 + 3] += nb * w.w;
            }
        }
        __syncthreads();
    }
    int pix = (ty0 + ly) * 64 + tx0 + lx;
    const float BNS = 0.9999950000374996f;   // 1/sqrt(1+1e-5)
    float* o = out + (size_t)e * 32 * PIX + pix;
#pragma unroll
    for (int c = 0; c < 32; c++) {
        float r = acc[c] * (gm[c] * BNS) + bt[c];
        o[(size_t)c * PIX] = fmaxf(r, 0.f);
    }
}

// ---------------- generic 3x3 conv, CIN->64 ---------------------------------
// CIRC: circular boundary + per-velocity (vy,vx) center shift (img = b*9+v)
// EPI 0: BN+ReLU    EPI 1: tanh(acc + x_t[b])   EPI 2: tanh(acc + up) + d_out
template <int CIN, bool CIRC, int EPI>
__global__ void __launch_bounds__(256, 2)
conv3_k(const float* __restrict__ in, const float* __restrict__ wt,
        const float* __restrict__ gm, const float* __restrict__ bt,
        const float* __restrict__ add, float* __restrict__ out,
        float* __restrict__ out2, int tstep) {
    __shared__ float sIn[400];     // 20x20 (halo 2: shift +/-1 plus conv +/-1)
    __shared__ float sW[576];      // [tap][cout=64], broadcast-read
    int tile = blockIdx.x, img = blockIdx.y;
    int ty0 = (tile >> 2) << 4, tx0 = (tile & 3) << 4;
    int tid = threadIdx.x, lx = tid & 15, ly = tid >> 4;
    int vy = 0, vx = 0;
    if (CIRC) { int v = img % NV; vy = v / 3 - 1; vx = v % 3 - 1; }
    const float* inImg = in + (size_t)img * CIN * PIX;
    float acc[64];
#pragma unroll
    for (int c = 0; c < 64; c++) acc[c] = 0.f;

    for (int k = 0; k < CIN; k++) {
        const float* inC = inImg + (size_t)k * PIX;
        for (int i = tid; i < 400; i += 256) {
            int ry = i / 20, rx = i - ry * 20;
            int gy = ty0 + ry - 2, gx = tx0 + rx - 2;
            float v_;
            if (CIRC) v_ = inC[(gy & 63) * 64 + (gx & 63)];
            else      v_ = (gy >= 0 && gy < 64 && gx >= 0 && gx < 64) ? inC[gy * 64 + gx] : 0.f;
            sIn[i] = v_;
        }
        for (int i = tid; i < 576; i += 256) {
            int c = i / 9, t9 = i - c * 9;
            sW[t9 * 64 + c] = wt[(c * CIN + k) * 9 + t9];
        }
        __syncthreads();
        // window top-left in smem coords: (ly+2) + (vy + dy - 1), dy in 0..2
        int cy = ly + 1 + vy, cx = lx + 1 + vx;
        float n[9];
#pragma unroll
        for (int dy = 0; dy < 3; dy++)
#pragma unroll
            for (int dx = 0; dx < 3; dx++)
                n[dy * 3 + dx] = sIn[(cy + dy) * 20 + cx + dx];
#pragma unroll
        for (int t9 = 0; t9 < 9; t9++) {
            const float4* w4 = (const float4*)(sW + t9 * 64);
            float nb = n[t9];
#pragma unroll
            for (int cc = 0; cc < 16; cc++) {
                float4 w = w4[cc];
                acc[cc * 4 + 0] += nb * w.x;
                acc[cc * 4 + 1] += nb * w.y;
                acc[cc * 4 + 2] += nb * w.z;
                acc[cc * 4 + 3] += nb * w.w;
            }
        }
        __syncthreads();
    }
    int pix = (ty0 + ly) * 64 + tx0 + lx;
    if (EPI == 0) {
        const float BNS = 0.9999950000374996f;
        float* o = out + (size_t)img * 64 * PIX + pix;
#pragma unroll
        for (int c = 0; c < 64; c++) {
            float r = acc[c] * (gm[c] * BNS) + bt[c];
            o[(size_t)c * PIX] = fmaxf(r, 0.f);
        }
    } else if (EPI == 1) {
        // h0 = tanh(x_t[b] + conv);  add = g_x base, b = img/9
        const float* a = add + ((size_t)(tstep * 4 + img / NV) * 64) * PIX + pix;
        float* o = out + (size_t)img * 64 * PIX + pix;
#pragma unroll
        for (int c = 0; c < 64; c++)
            o[(size_t)c * PIX] = tanhf(acc[c] + a[(size_t)c * PIX]);
    } else {
        // h1 = tanh(up + conv); also write d_out[v][b][c][t][pix]
        const float* a = add + (size_t)img * 64 * PIX + pix;
        float* o = out + (size_t)img * 64 * PIX + pix;
        int v = img % NV, bb = img / NV;
        float* o2 = out2 + ((size_t)(v * 4 + bb) * 64 * 8 + tstep) * PIX + pix;
#pragma unroll
        for (int c = 0; c < 64; c++) {
            float val = tanhf(acc[c] + a[(size_t)c * PIX]);
            o[(size_t)c * PIX] = val;
            o2[(size_t)c * 8 * PIX] = val;
        }
    }
}

// ---------------- host driver ----------------------------------------------
extern "C" void kernel_launch(void* const* d_in, const int* in_sizes, int n_in,
                              void* d_out, int out_size) {
    (void)in_sizes; (void)n_in; (void)out_size;
    const float* u   = (const float*)d_in[0];
    const float* w1  = (const float*)d_in[1];
    const float* g1  = (const float*)d_in[2];
    const float* b1  = (const float*)d_in[3];
    const float* w2  = (const float*)d_in[4];
    const float* g2  = (const float*)d_in[5];
    const float* b2  = (const float*)d_in[6];
    const float* w3  = (const float*)d_in[7];
    const float* g3  = (const float*)d_in[8];
    const float* b3  = (const float*)d_in[9];
    const float* wul = (const float*)d_in[10];
    const float* gul = (const float*)d_in[11];
    const float* bul = (const float*)d_in[12];
    const float* wh0 = (const float*)d_in[13];
    const float* wh1 = (const float*)d_in[14];
    float* out = (float*)d_out;

    static float *px = nullptr, *pe1 = nullptr, *pe2 = nullptr,
                 *ph0 = nullptr, *ph1 = nullptr, *pup = nullptr;
    if (!px) {   // pointer caching only (no work skipped); runs on the
                 // pre-capture correctness call, so capture sees pure launches
        cudaGetSymbolAddress((void**)&px,  g_x);
        cudaGetSymbolAddress((void**)&pe1, g_e1);
        cudaGetSymbolAddress((void**)&pe2, g_e2);
        cudaGetSymbolAddress((void**)&ph0, g_h0);
        cudaGetSymbolAddress((void**)&ph1, g_h1);
        cudaGetSymbolAddress((void**)&pup, g_up);
    }
    const size_t HSZ = 36ull * 64 * PIX;

    // h0/h1 parity-0 = 9,437,184 floats each = 2,359,296 float4 = 9216 * 256
    zero_init_k<<<9216, 256>>>();

    // encoder for all (t,b) up front
    conv1_k<<<dim3(16, 32), 256>>>(u, w1, g1, b1, pe1);
    conv3_k<32, false, 0><<<dim3(16, 32), 256>>>(pe1, w2, g2, b2, nullptr, pe2, nullptr, 0);
    conv3_k<64, false, 0><<<dim3(16, 32), 256>>>(pe2, w3, g3, b3, nullptr, px, nullptr, 0);

    // recurrent steps
    for (int t = 0; t < 8; t++) {
        int rp = t & 1, wp = 1 - rp;
        // h0 = tanh(x_t + circ-shift conv(h0_old, w_h0))
        conv3_k<64, true, 1><<<dim3(16, 36), 256>>>(ph0 + rp * HSZ, wh0, nullptr, nullptr,
                                                    px, ph0 + wp * HSZ, nullptr, t);
        // up = relu(bn(conv(h0_new, w_ul)))  (zero pad)
        conv3_k<64, false, 0><<<dim3(16, 36), 256>>>(ph0 + wp * HSZ, wul, gul, bul,
                                                     nullptr, pup, nullptr, 0);
        // h1 = tanh(up + circ-shift conv(h1_old, w_h1)); fused d_out store
        conv3_k<64, true, 2><<<dim3(16, 36), 256>>>(ph1 + rp * HSZ, wh1, nullptr, nullptr,
                                                    pup, ph1 + wp * HSZ, out, t);
    }
}

// round 2
// speedup vs baseline: 1.9594x; 1.9594x over previous
#include <cuda_runtime.h>
#include <math.h>
#include <stdint.h>

#define PIX 4096
#define NV 9

// ---------------- scratch (device globals; no allocations allowed) ----------
__device__ float g_x [32ull*64*PIX];   // encoder output x, [t*4+b][c][pix]
__device__ float g_e1[32ull*32*PIX];   // encoder stage 1
__device__ float g_e2[32ull*64*PIX];   // encoder stage 2
__device__ float g_h0[2ull*36*64*PIX]; // ping-pong h0, [p][b*9+v][c][pix]
__device__ float g_h1[2ull*36*64*PIX]; // ping-pong h1
__device__ float g_up[36ull*64*PIX];   // layer-1 conv_u output

__global__ void zero_init_k() {
    size_t i = (size_t)blockIdx.x * 256 + threadIdx.x;   // 9216*256 threads
    float4 z = make_float4(0.f, 0.f, 0.f, 0.f);
    reinterpret_cast<float4*>(g_h0)[i] = z;
    reinterpret_cast<float4*>(g_h1)[i] = z;
}

// ---------------- packed f32x2 helpers --------------------------------------
__device__ __forceinline__ unsigned long long ffma2(unsigned long long a,
                                                    unsigned long long b,
                                                    unsigned long long c) {
    unsigned long long d;
    asm("fma.rn.f32x2 %0, %1, %2, %3;" : "=l"(d) : "l"(a), "l"(b), "l"(c));
    return d;
}
__device__ __forceinline__ unsigned long long pack_dup(float v) {
    unsigned long long d; unsigned r = __float_as_uint(v);
    asm("mov.b64 %0, {%1, %1};" : "=l"(d) : "r"(r));
    return d;
}
__device__ __forceinline__ void unpack2(unsigned long long v, float& lo, float& hi) {
    unsigned a, b;
    asm("mov.b64 {%0, %1}, %2;" : "=r"(a), "=r"(b) : "l"(v));
    lo = __uint_as_float(a); hi = __uint_as_float(b);
}
__device__ __forceinline__ void cp4(uint32_t s, const float* g, int srcsz) {
    asm volatile("cp.async.ca.shared.global [%0], [%1], 4, %2;"
                 :: "r"(s), "l"(g), "r"(srcsz));
}
__device__ __forceinline__ void cp_commit() { asm volatile("cp.async.commit_group;"); }
__device__ __forceinline__ void cp_wait()   { asm volatile("cp.async.wait_all;" ::: "memory"); }

// ---------------- encoder conv1: 3->32, 5x5, zero pad 2, BN+ReLU ------------
__global__ void __launch_bounds__(256, 2)
conv1_k(const float* __restrict__ u, const float* __restrict__ wt,
        const float* __restrict__ gm, const float* __restrict__ bt,
        float* __restrict__ out) {
    __shared__ float sIn[400];       // 20x20 tile (halo 2)
    __shared__ float sW[25 * 32];    // [tap][cout]
    int tile = blockIdx.x, e = blockIdx.y;      // e = t*4 + b
    int tstep = e >> 2, bb = e & 3;
    int ty0 = (tile >> 2) << 4, tx0 = (tile & 3) << 4;
    int tid = threadIdx.x, lx = tid & 15, ly = tid >> 4;
    const float* inImg = u + (size_t)(bb * 8 + tstep) * 3 * PIX;  // u[b][t][c]
    float acc[32];
#pragma unroll
    for (int c = 0; c < 32; c++) acc[c] = 0.f;

    for (int k = 0; k < 3; k++) {
        const float* inC = inImg + (size_t)k * PIX;
        for (int i = tid; i < 400; i += 256) {
            int ry = i / 20, rx = i - ry * 20;
            int gy = ty0 + ry - 2, gx = tx0 + rx - 2;
            sIn[i] = (gy >= 0 && gy < 64 && gx >= 0 && gx < 64) ? inC[gy * 64 + gx] : 0.f;
        }
        for (int i = tid; i < 800; i += 256) {
            int c = i / 25, t5 = i - c * 25;
            sW[t5 * 32 + c] = wt[(c * 3 + k) * 25 + t5];
        }
        __syncthreads();
        float n[25];
#pragma unroll
        for (int dy = 0; dy < 5; dy++)
#pragma unroll
            for (int dx = 0; dx < 5; dx++)
                n[dy * 5 + dx] = sIn[(ly + dy) * 20 + lx + dx];
#pragma unroll
        for (int t5 = 0; t5 < 25; t5++) {
            const float4* w4 = (const float4*)(sW + t5 * 32);
            float nb = n[t5];
#pragma unroll
            for (int cc = 0; cc < 8; cc++) {
                float4 w = w4[cc];
                acc[cc * 4 + 0] += nb * w.x;
                acc[cc * 4 + 1] += nb * w.y;
                acc[cc * 4 + 2] += nb * w.z;
                acc[cc * 4 + 3] += nb * w.w;
            }
        }
        __syncthreads();
    }
    int pix = (ty0 + ly) * 64 + tx0 + lx;
    const float BNS = 0.9999950000374996f;   // 1/sqrt(1+1e-5)
    float* o = out + (size_t)e * 32 * PIX + pix;
#pragma unroll
    for (int c = 0; c < 32; c++) {
        float r = acc[c] * (gm[c] * BNS) + bt[c];
        o[(size_t)c * PIX] = fmaxf(r, 0.f);
    }
}

// ---------------- quad-tiled 3x3 conv, CIN->64, f32x2 FMA -------------------
// Block: 256 thr, 32x32 output tile, 16 couts (blockIdx.y = cout group).
// Each thread: 2x2 pixel quad x 16 couts (as 8 f32x2 cout-pairs).
// CIRC: circular boundary + per-velocity (vy,vx) center shift (img = b*9+v)
// EPI 0: BN+ReLU    EPI 1: tanh(acc + x_t[b])   EPI 2: tanh(acc + up) + d_out
template <int CIN, bool CIRC, int EPI>
__global__ void __launch_bounds__(256, 2)
conv3q_k(const float* __restrict__ in, const float* __restrict__ wt,
         const float* __restrict__ gm, const float* __restrict__ bt,
         const float* __restrict__ add, float* __restrict__ out,
         float* __restrict__ out2, int tstep) {
    __shared__ float sIn[2][1296];                 // 36x36 tile (halo 2), double-buffered
    __shared__ __align__(16) float sW[CIN * 144];  // [cin][tap][cout16]
    int tile = blockIdx.x;                  // 0..3 -> 2x2 of 32x32 tiles
    int cout0 = blockIdx.y << 4;            // cout group * 16
    int img = blockIdx.z;
    int ty0 = (tile >> 1) << 5, tx0 = (tile & 1) << 5;
    int tid = threadIdx.x, lx = tid & 15, ly = tid >> 4;
    int qy = ly << 1, qx = lx << 1;         // quad base within tile
    int vy = 0, vx = 0;
    if (CIRC) { int v = img % NV; vy = v / 3 - 1; vx = v % 3 - 1; }
    const float* inImg = in + (size_t)img * CIN * PIX;

    // ---- preload ALL weights for this cout group ----
#pragma unroll 4
    for (int i = tid; i < CIN * 144; i += 256) {
        int k = i / 144, r = i - k * 144;
        int tap = r >> 4, c = r & 15;
        sW[i] = wt[((size_t)(cout0 + c) * CIN + k) * 9 + tap];
    }

    // ---- stage channel 0 ----
    uint32_t sInA0 = (uint32_t)__cvta_generic_to_shared(&sIn[0][0]);
    uint32_t sInA1 = (uint32_t)__cvta_generic_to_shared(&sIn[1][0]);
    {
        const float* inC = inImg;
#pragma unroll
        for (int j = 0; j < 6; j++) {
            int i = tid + j * 256;
            if (j < 5 || i < 1296) {
                int r = i / 36, c = i - r * 36;
                int gy = ty0 + r - 2, gx = tx0 + c - 2;
                if (CIRC) cp4(sInA0 + i * 4, inC + ((gy & 63) * 64 + (gx & 63)), 4);
                else {
                    int ok = (gy >= 0 && gy < 64 && gx >= 0 && gx < 64) ? 4 : 0;
                    cp4(sInA0 + i * 4, inC + (gy * 64 + gx), ok);
                }
            }
        }
        cp_commit();
    }
    cp_wait();
    __syncthreads();

    unsigned long long acc[8][4];
#pragma unroll
    for (int cp = 0; cp < 8; cp++)
#pragma unroll
        for (int p = 0; p < 4; p++) acc[cp][p] = 0ull;

    int r0 = qy + vy + 1, c0 = qx + vx + 1;   // window top-left in smem coords

    for (int k = 0; k < CIN; k++) {
        // prefetch next channel into other buffer
        if (k + 1 < CIN) {
            const float* inC = inImg + (size_t)(k + 1) * PIX;
            uint32_t dst = ((k + 1) & 1) ? sInA1 : sInA0;
#pragma unroll
            for (int j = 0; j < 6; j++) {
                int i = tid + j * 256;
                if (j < 5 || i < 1296) {
                    int r = i / 36, c = i - r * 36;
                    int gy = ty0 + r - 2, gx = tx0 + c - 2;
                    if (CIRC) cp4(dst + i * 4, inC + ((gy & 63) * 64 + (gx & 63)), 4);
                    else {
                        int ok = (gy >= 0 && gy < 64 && gx >= 0 && gx < 64) ? 4 : 0;
                        cp4(dst + i * 4, inC + (gy * 64 + gx), ok);
                    }
                }
            }
            cp_commit();
        }
        // compute on current buffer
        const float* buf = sIn[k & 1];
        unsigned long long nn[16];
#pragma unroll
        for (int i = 0; i < 4; i++)
#pragma unroll
            for (int j = 0; j < 4; j++)
                nn[i * 4 + j] = pack_dup(buf[(r0 + i) * 36 + (c0 + j)]);
        const float* W = sW + k * 144;
#pragma unroll
        for (int ty = 0; ty < 3; ty++)
#pragma unroll
            for (int tx = 0; tx < 3; tx++) {
                const unsigned long long* w2 =
                    (const unsigned long long*)(W + (ty * 3 + tx) * 16);
#pragma unroll
                for (int cp = 0; cp < 8; cp++) {
                    unsigned long long w = w2[cp];
#pragma unroll
                    for (int py = 0; py < 2; py++)
#pragma unroll
                        for (int px = 0; px < 2; px++)
                            acc[cp][py * 2 + px] =
                                ffma2(w, nn[(py + ty) * 4 + (px + tx)], acc[cp][py * 2 + px]);
                }
            }
        cp_wait();
        __syncthreads();
    }

    // ---- epilogue ----
    int py0 = ty0 + qy, px0 = tx0 + qx;           // global pixel base
    const float BNS = 0.9999950000374996f;
#pragma unroll
    for (int cp = 0; cp < 8; cp++) {
        float lo[4], hi[4];
#pragma unroll
        for (int p = 0; p < 4; p++) unpack2(acc[cp][p], lo[p], hi[p]);
        int cA = cout0 + 2 * cp, cB = cA + 1;
        if (EPI == 0) {
            float sA = gm[cA] * BNS, bA = bt[cA];
            float sB = gm[cB] * BNS, bB = bt[cB];
            float* oA = out + ((size_t)img * 64 + cA) * PIX;
            float* oB = out + ((size_t)img * 64 + cB) * PIX;
#pragma unroll
            for (int py = 0; py < 2; py++) {
                int pix = (py0 + py) * 64 + px0;
                float2 vA = make_float2(fmaxf(lo[py*2+0]*sA+bA, 0.f),
                                        fmaxf(lo[py*2+1]*sA+bA, 0.f));
                float2 vB = make_float2(fmaxf(hi[py*2+0]*sB+bB, 0.f),
                                        fmaxf(hi[py*2+1]*sB+bB, 0.f));
                *(float2*)(oA + pix) = vA;
                *(float2*)(oB + pix) = vB;
            }
        } else if (EPI == 1) {
            const float* aB = add + (size_t)(tstep * 4 + img / NV) * 64 * PIX;
            float* oA = out + ((size_t)img * 64 + cA) * PIX;
            float* oB = out + ((size_t)img * 64 + cB) * PIX;
#pragma unroll
            for (int py = 0; py < 2; py++) {
                int pix = (py0 + py) * 64 + px0;
                float2 xA = *(const float2*)(aB + (size_t)cA * PIX + pix);
                float2 xB = *(const float2*)(aB + (size_t)cB * PIX + pix);
                float2 vA = make_float2(tanhf(lo[py*2+0] + xA.x), tanhf(lo[py*2+1] + xA.y));
                float2 vB = make_float2(tanhf(hi[py*2+0] + xB.x), tanhf(hi[py*2+1] + xB.y));
                *(float2*)(oA + pix) = vA;
                *(float2*)(oB + pix) = vB;
            }
        } else {
            const float* aB = add + (size_t)img * 64 * PIX;
            float* oA = out + ((size_t)img * 64 + cA) * PIX;
            float* oB = out + ((size_t)img * 64 + cB) * PIX;
            int v = img % NV, bb = img / NV;
            float* o2 = out2 + ((size_t)(v * 4 + bb) * 64 * 8 + tstep) * PIX;
#pragma unroll
            for (int py = 0; py < 2; py++) {
                int pix = (py0 + py) * 64 + px0;
                float2 xA = *(const float2*)(aB + (size_t)cA * PIX + pix);
                float2 xB = *(const float2*)(aB + (size_t)cB * PIX + pix);
                float2 vA = make_float2(tanhf(lo[py*2+0] + xA.x), tanhf(lo[py*2+1] + xA.y));
                float2 vB = make_float2(tanhf(hi[py*2+0] + xB.x), tanhf(hi[py*2+1] + xB.y));
                *(float2*)(oA + pix) = vA;
                *(float2*)(oB + pix) = vB;
                *(float2*)(o2 + (size_t)cA * 8 * PIX + pix) = vA;
                *(float2*)(o2 + (size_t)cB * 8 * PIX + pix) = vB;
            }
        }
    }
}

// ---------------- host driver ----------------------------------------------
extern "C" void kernel_launch(void* const* d_in, const int* in_sizes, int n_in,
                              void* d_out, int out_size) {
    (void)in_sizes; (void)n_in; (void)out_size;
    const float* u   = (const float*)d_in[0];
    const float* w1  = (const float*)d_in[1];
    const float* g1  = (const float*)d_in[2];
    const float* b1  = (const float*)d_in[3];
    const float* w2  = (const float*)d_in[4];
    const float* g2  = (const float*)d_in[5];
    const float* b2  = (const float*)d_in[6];
    const float* w3  = (const float*)d_in[7];
    const float* g3  = (const float*)d_in[8];
    const float* b3  = (const float*)d_in[9];
    const float* wul = (const float*)d_in[10];
    const float* gul = (const float*)d_in[11];
    const float* bul = (const float*)d_in[12];
    const float* wh0 = (const float*)d_in[13];
    const float* wh1 = (const float*)d_in[14];
    float* out = (float*)d_out;

    static float *px = nullptr, *pe1 = nullptr, *pe2 = nullptr,
                 *ph0 = nullptr, *ph1 = nullptr, *pup = nullptr;
    if (!px) {   // pointer caching only; runs on the pre-capture call
        cudaGetSymbolAddress((void**)&px,  g_x);
        cudaGetSymbolAddress((void**)&pe1, g_e1);
        cudaGetSymbolAddress((void**)&pe2, g_e2);
        cudaGetSymbolAddress((void**)&ph0, g_h0);
        cudaGetSymbolAddress((void**)&ph1, g_h1);
        cudaGetSymbolAddress((void**)&pup, g_up);
    }
    const size_t HSZ = 36ull * 64 * PIX;

    zero_init_k<<<9216, 256>>>();

    // encoder for all (t,b) up front
    conv1_k<<<dim3(16, 32), 256>>>(u, w1, g1, b1, pe1);
    conv3q_k<32, false, 0><<<dim3(4, 4, 32), 256>>>(pe1, w2, g2, b2, nullptr, pe2, nullptr, 0);
    conv3q_k<64, false, 0><<<dim3(4, 4, 32), 256>>>(pe2, w3, g3, b3, nullptr, px, nullptr, 0);

    // recurrent steps
    for (int t = 0; t < 8; t++) {
        int rp = t & 1, wp = 1 - rp;
        // h0 = tanh(x_t + circ-shift conv(h0_old, w_h0))
        conv3q_k<64, true, 1><<<dim3(4, 4, 36), 256>>>(ph0 + rp * HSZ, wh0, nullptr, nullptr,
                                                       px, ph0 + wp * HSZ, nullptr, t);
        // up = relu(bn(conv(h0_new, w_ul)))  (zero pad)
        conv3q_k<64, false, 0><<<dim3(4, 4, 36), 256>>>(ph0 + wp * HSZ, wul, gul, bul,
                                                        nullptr, pup, nullptr, 0);
        // h1 = tanh(up + circ-shift conv(h1_old, w_h1)); fused d_out store
        conv3q_k<64, true, 2><<<dim3(4, 4, 36), 256>>>(ph1 + rp * HSZ, wh1, nullptr, nullptr,
                                                       pup, ph1 + wp * HSZ, out, t);
    }
}

// round 3
// speedup vs baseline: 3.3303x; 1.6997x over previous
#include <cuda_runtime.h>
#include <math.h>
#include <stdint.h>

#define PIX 4096
#define NV 9

// ---------------- scratch (device globals; no allocations allowed) ----------
__device__ float g_x  [32ull*64*PIX];   // encoder output x (fp32 addend)
__device__ float g_e1 [32ull*32*PIX];   // encoder stage 1 (tf32-rounded)
__device__ float g_e2 [32ull*64*PIX];   // encoder stage 2 (tf32-rounded)
__device__ float g_h0 [2ull*36*64*PIX]; // ping-pong h0 (tf32-rounded)
__device__ float g_h1 [2ull*36*64*PIX]; // ping-pong h1 (tf32-rounded)
__device__ float g_up [36ull*64*PIX];   // layer-1 conv_u output (fp32 addend)
// permuted tf32 weights: [tap][k][nperm], nperm=(n%8)*8+n/8
__device__ float g_wp2 [9*32*64];
__device__ float g_wp3 [9*64*64];
__device__ float g_wpul[9*64*64];
__device__ float g_wph0[9*64*64];
__device__ float g_wph1[9*64*64];

__global__ void zero_init_k() {
    size_t i = (size_t)blockIdx.x * 256 + threadIdx.x;   // 9216*256 threads
    float4 z = make_float4(0.f, 0.f, 0.f, 0.f);
    reinterpret_cast<float4*>(g_h0)[i] = z;
    reinterpret_cast<float4*>(g_h1)[i] = z;
}

// ---------------- helpers ----------------------------------------------------
__device__ __forceinline__ float rna(float x) {
    unsigned r;
    asm("cvt.rna.tf32.f32 %0, %1;" : "=r"(r) : "f"(x));
    return __uint_as_float(r);
}
__device__ __forceinline__ void cp16(uint32_t s, const float* g, int srcsz) {
    asm volatile("cp.async.ca.shared.global [%0], [%1], 16, %2;"
                 :: "r"(s), "l"(g), "r"(srcsz));
}
__device__ __forceinline__ void cp8(uint32_t s, const float* g, int srcsz) {
    asm volatile("cp.async.ca.shared.global [%0], [%1], 8, %2;"
                 :: "r"(s), "l"(g), "r"(srcsz));
}
__device__ __forceinline__ void cp_commit() { asm volatile("cp.async.commit_group;"); }
__device__ __forceinline__ void cp_wait()   { asm volatile("cp.async.wait_all;" ::: "memory"); }

__device__ __forceinline__ void mma8(float* d, unsigned a0, unsigned a1,
                                     unsigned a2, unsigned a3,
                                     unsigned b0, unsigned b1) {
    asm("mma.sync.aligned.m16n8k8.row.col.f32.tf32.tf32.f32 "
        "{%0,%1,%2,%3},{%4,%5,%6,%7},{%8,%9},{%0,%1,%2,%3};"
        : "+f"(d[0]), "+f"(d[1]), "+f"(d[2]), "+f"(d[3])
        : "r"(a0), "r"(a1), "r"(a2), "r"(a3), "r"(b0), "r"(b1));
}

// ---------------- weight permute+round prep ----------------------------------
__global__ void prep_w_k(const float* __restrict__ w2, const float* __restrict__ w3,
                         const float* __restrict__ wul, const float* __restrict__ wh0,
                         const float* __restrict__ wh1) {
    int idx = blockIdx.x * 256 + threadIdx.x;
    int conv = blockIdx.y;
    const float* src; float* dst; int CIN;
    if      (conv == 0) { src = w2;  dst = g_wp2;  CIN = 32; }
    else if (conv == 1) { src = w3;  dst = g_wp3;  CIN = 64; }
    else if (conv == 2) { src = wul; dst = g_wpul; CIN = 64; }
    else if (conv == 3) { src = wh0; dst = g_wph0; CIN = 64; }
    else                { src = wh1; dst = g_wph1; CIN = 64; }
    int total = 9 * CIN * 64;
    if (idx >= total) return;
    int tap = idx / (CIN * 64), rem = idx - tap * (CIN * 64);
    int k = rem / 64, np = rem & 63;
    int n = ((np & 7) << 3) + (np >> 3);
    dst[idx] = rna(src[((size_t)n * CIN + k) * 9 + tap]);
}

// ---------------- encoder conv1: 3->32, 5x5, zero pad 2, BN+ReLU -------------
__global__ void __launch_bounds__(256, 2)
conv1_k(const float* __restrict__ u, const float* __restrict__ wt,
        const float* __restrict__ gm, const float* __restrict__ bt,
        float* __restrict__ out) {
    __shared__ float sIn[400];       // 20x20 tile (halo 2)
    __shared__ float sW[25 * 32];    // [tap][cout]
    int tile = blockIdx.x, e = blockIdx.y;      // e = t*4 + b
    int tstep = e >> 2, bb = e & 3;
    int ty0 = (tile >> 2) << 4, tx0 = (tile & 3) << 4;
    int tid = threadIdx.x, lx = tid & 15, ly = tid >> 4;
    const float* inImg = u + (size_t)(bb * 8 + tstep) * 3 * PIX;  // u[b][t][c]
    float acc[32];
#pragma unroll
    for (int c = 0; c < 32; c++) acc[c] = 0.f;

    for (int k = 0; k < 3; k++) {
        const float* inC = inImg + (size_t)k * PIX;
        for (int i = tid; i < 400; i += 256) {
            int ry = i / 20, rx = i - ry * 20;
            int gy = ty0 + ry - 2, gx = tx0 + rx - 2;
            sIn[i] = (gy >= 0 && gy < 64 && gx >= 0 && gx < 64) ? inC[gy * 64 + gx] : 0.f;
        }
        for (int i = tid; i < 800; i += 256) {
            int c = i / 25, t5 = i - c * 25;
            sW[t5 * 32 + c] = wt[(c * 3 + k) * 25 + t5];
        }
        __syncthreads();
        float n[25];
#pragma unroll
        for (int dy = 0; dy < 5; dy++)
#pragma unroll
            for (int dx = 0; dx < 5; dx++)
                n[dy * 5 + dx] = sIn[(ly + dy) * 20 + lx + dx];
#pragma unroll
        for (int t5 = 0; t5 < 25; t5++) {
            const float4* w4 = (const float4*)(sW + t5 * 32);
            float nb = n[t5];
#pragma unroll
            for (int cc = 0; cc < 8; cc++) {
                float4 w = w4[cc];
                acc[cc * 4 + 0] += nb * w.x;
                acc[cc * 4 + 1] += nb * w.y;
                acc[cc * 4 + 2] += nb * w.z;
                acc[cc * 4 + 3] += nb * w.w;
            }
        }
        __syncthreads();
    }
    int pix = (ty0 + ly) * 64 + tx0 + lx;
    const float BNS = 0.9999950000374996f;   // 1/sqrt(1+1e-5)
    float* o = out + (size_t)e * 32 * PIX + pix;
#pragma unroll
    for (int c = 0; c < 32; c++) {
        float r = acc[c] * (gm[c] * BNS) + bt[c];
        o[(size_t)c * PIX] = rna(fmaxf(r, 0.f));   // feeds mma -> tf32 round
    }
}

// ---------------- tensor-core 3x3 conv, CIN->64 -------------------------------
// Block: 256 thr = 8 warps; 4 output rows (256 px), all 64 couts.
// Warp w: output row ry0 + (w>>1), x half (w&1)*32; M=32 px (2 m16 tiles), N=64.
// A staged in smem [cin][8 rows x 72 cols], k-stride 584 words (conflict-free).
// Taps = smem base-offset shifts; circular wrap + velocity shift applied at staging.
// EPI 0: BN+ReLU (RNA opt)   EPI 1: tanh(acc+x), rna   EPI 2: tanh(acc+up), rna + d_out
template <int CIN, bool CIRC, int EPI, bool RNA>
__global__ void __launch_bounds__(256, 1)
convmma_k(const float* __restrict__ in, const float* __restrict__ wp,
          const float* __restrict__ gm, const float* __restrict__ bt,
          const float* __restrict__ add, float* __restrict__ out,
          float* __restrict__ out2, int tstep) {
    constexpr int TAPCH = (CIN == 64) ? 3 : 9;   // taps per W chunk
    constexpr int NCH = 9 / TAPCH;
    constexpr int AROW = 584;                    // k-stride (words)
    extern __shared__ float sm[];
    float* As = sm;                      // [CIN][AROW]
    float* Ws = sm + CIN * AROW;         // [TAPCH][CIN][64]

    int img = blockIdx.y, ry0 = blockIdx.x * 4;
    int tid = threadIdx.x, w = tid >> 5, qp = (tid >> 2) & 7, qt = tid & 3;
    int vy = 0, vx = 0;
    if (CIRC) { int v = img % NV; vy = v / 3 - 1; vx = v % 3 - 1; }
    const float* inI = in + (size_t)img * CIN * PIX;
    uint32_t smA = (uint32_t)__cvta_generic_to_shared(As);
    uint32_t smW = (uint32_t)__cvta_generic_to_shared(Ws);

    // ---- stage A: rows ry0-2..ry0+3, cols -2..65 (wrap or zero) ----
    for (int i = tid; i < CIN * 144; i += 256) {     // CIN*8*18 slots
        int k = i / 144, rem = i - k * 144, r = rem / 18, s = rem - r * 18;
        int gy = ry0 + r - 2;
        bool rowok = true;
        if (CIRC) gy &= 63; else rowok = (gy >= 0 && gy < 64);
        const float* srow = inI + (size_t)k * PIX + gy * 64;
        uint32_t dst = smA + (uint32_t)(k * AROW + r * 72) * 4u;
        if (s < 16)      cp16(dst + (4 + s * 4) * 4, srow + s * 4, rowok ? 16 : 0);
        else if (s == 16) cp8(dst + 2 * 4, srow + 62, CIRC ? 8 : 0);   // gx -2,-1
        else              cp8(dst + 68 * 4, srow,     CIRC ? 8 : 0);   // gx 64,65
    }
    // ---- stage W chunk 0 ----
    {
        const float4* src = (const float4*)wp;
        for (int i = tid; i < TAPCH * CIN * 16; i += 256)
            cp16(smW + i * 16, (const float*)(src + i), 16);
    }
    cp_commit(); cp_wait(); __syncthreads();

    float acc[2][8][4];
#pragma unroll
    for (int mt = 0; mt < 2; mt++)
#pragma unroll
        for (int g = 0; g < 8; g++)
#pragma unroll
            for (int j = 0; j < 4; j++) acc[mt][g][j] = 0.f;

    int mbase = (2 + (w >> 1)) * 72 + 4 + 32 * (w & 1) + qp;
    const unsigned* Au = (const unsigned*)As;

    for (int ch = 0; ch < NCH; ch++) {
        if (ch) {
            __syncthreads();
            const float4* src = (const float4*)(wp + (size_t)ch * TAPCH * CIN * 64);
            for (int i = tid; i < TAPCH * CIN * 16; i += 256)
                cp16(smW + i * 16, (const float*)(src + i), 16);
            cp_commit(); cp_wait(); __syncthreads();
        }
#pragma unroll
        for (int tapc = 0; tapc < TAPCH; tapc++) {
            int tap = ch * TAPCH + tapc;
            int dy = tap / 3, dx = tap - dy * 3;
            int apos = mbase + (dy - 1 + vy) * 72 + (dx - 1 + vx);
#pragma unroll
            for (int ks = 0; ks < CIN / 8; ks++) {
                int kr0 = ks * 8 + qt, kr1 = kr0 + 4;
                const uint4* B0 = (const uint4*)(Ws + (tapc * CIN + kr0) * 64 + qp * 8);
                const uint4* B1 = (const uint4*)(Ws + (tapc * CIN + kr1) * 64 + qp * 8);
                uint4 l0 = B0[0], l1 = B0[1], h0 = B1[0], h1 = B1[1];
                unsigned blo[8] = {l0.x, l0.y, l0.z, l0.w, l1.x, l1.y, l1.z, l1.w};
                unsigned bhi[8] = {h0.x, h0.y, h0.z, h0.w, h1.x, h1.y, h1.z, h1.w};
                unsigned a[2][4];
#pragma unroll
                for (int mt = 0; mt < 2; mt++) {
                    int base = apos + mt * 16;
                    a[mt][0] = Au[kr0 * AROW + base];
                    a[mt][1] = Au[kr0 * AROW + base + 8];
                    a[mt][2] = Au[kr1 * AROW + base];
                    a[mt][3] = Au[kr1 * AROW + base + 8];
                }
#pragma unroll
                for (int g = 0; g < 8; g++)
#pragma unroll
                    for (int mt = 0; mt < 2; mt++)
                        mma8(acc[mt][g], a[mt][0], a[mt][1], a[mt][2], a[mt][3],
                             blo[g], bhi[g]);
            }
        }
    }

    // ---- epilogue ----
    int y = ry0 + (w >> 1);
    int xg = 32 * (w & 1) + qp;
    const float BNS = 0.9999950000374996f;
#pragma unroll
    for (int mt = 0; mt < 2; mt++) {
        int x0 = xg + mt * 16;
        int pixA = y * 64 + x0, pixB = pixA + 8;
#pragma unroll
        for (int g = 0; g < 8; g++) {
            int c = g * 8 + qt * 2;
            float v0 = acc[mt][g][0], v1 = acc[mt][g][1];
            float v2 = acc[mt][g][2], v3 = acc[mt][g][3];
            if (EPI == 0) {
                float s0 = gm[c] * BNS, s1 = gm[c + 1] * BNS;
                float o0 = bt[c], o1 = bt[c + 1];
                float r0 = fmaxf(v0 * s0 + o0, 0.f), r1 = fmaxf(v1 * s1 + o1, 0.f);
                float r2 = fmaxf(v2 * s0 + o0, 0.f), r3 = fmaxf(v3 * s1 + o1, 0.f);
                float* p0 = out + ((size_t)img * 64 + c) * PIX;
                float* p1 = p0 + PIX;
                if (RNA) { r0 = rna(r0); r1 = rna(r1); r2 = rna(r2); r3 = rna(r3); }
                p0[pixA] = r0; p0[pixB] = r2; p1[pixA] = r1; p1[pixB] = r3;
            } else if (EPI == 1) {
                const float* a0 = add + ((size_t)(tstep * 4 + img / NV) * 64 + c) * PIX;
                const float* a1 = a0 + PIX;
                float t0 = tanhf(v0 + a0[pixA]), t1 = tanhf(v1 + a1[pixA]);
                float t2 = tanhf(v2 + a0[pixB]), t3 = tanhf(v3 + a1[pixB]);
                float* p0 = out + ((size_t)img * 64 + c) * PIX;
                float* p1 = p0 + PIX;
                p0[pixA] = rna(t0); p0[pixB] = rna(t2);
                p1[pixA] = rna(t1); p1[pixB] = rna(t3);
            } else {
                const float* a0 = add + ((size_t)img * 64 + c) * PIX;
                const float* a1 = a0 + PIX;
                float t0 = tanhf(v0 + a0[pixA]), t1 = tanhf(v1 + a1[pixA]);
                float t2 = tanhf(v2 + a0[pixB]), t3 = tanhf(v3 + a1[pixB]);
                float* p0 = out + ((size_t)img * 64 + c) * PIX;
                float* p1 = p0 + PIX;
                p0[pixA] = rna(t0); p0[pixB] = rna(t2);
                p1[pixA] = rna(t1); p1[pixB] = rna(t3);
                int v9 = img % NV, bb = img / NV;
                float* q0 = out2 + (((size_t)(v9 * 4 + bb) * 64 + c) * 8 + tstep) * PIX;
                float* q1 = q0 + 8 * PIX;
                q0[pixA] = t0; q0[pixB] = t2; q1[pixA] = t1; q1[pixB] = t3;
            }
        }
    }
}

// ---------------- host driver -------------------------------------------------
extern "C" void kernel_launch(void* const* d_in, const int* in_sizes, int n_in,
                              void* d_out, int out_size) {
    (void)in_sizes; (void)n_in; (void)out_size;
    const float* u   = (const float*)d_in[0];
    const float* w1  = (const float*)d_in[1];
    const float* g1  = (const float*)d_in[2];
    const float* b1  = (const float*)d_in[3];
    const float* w2  = (const float*)d_in[4];
    const float* g2  = (const float*)d_in[5];
    const float* b2  = (const float*)d_in[6];
    const float* w3  = (const float*)d_in[7];
    const float* g3  = (const float*)d_in[8];
    const float* b3  = (const float*)d_in[9];
    const float* wul = (const float*)d_in[10];
    const float* gul = (const float*)d_in[11];
    const float* bul = (const float*)d_in[12];
    const float* wh0 = (const float*)d_in[13];
    const float* wh1 = (const float*)d_in[14];
    float* out = (float*)d_out;

    const int SM32B = (32 * 584 + 9 * 32 * 64) * 4;   // 148480
    const int SM64B = (64 * 584 + 3 * 64 * 64) * 4;   // 198656

    static float *px = nullptr, *pe1 = nullptr, *pe2 = nullptr,
                 *ph0 = nullptr, *ph1 = nullptr, *pup = nullptr,
                 *pw2 = nullptr, *pw3 = nullptr, *pwul = nullptr,
                 *pwh0 = nullptr, *pwh1 = nullptr;
    if (!px) {   // pointer caching + attribute setup; runs on the pre-capture call
        cudaGetSymbolAddress((void**)&px,   g_x);
        cudaGetSymbolAddress((void**)&pe1,  g_e1);
        cudaGetSymbolAddress((void**)&pe2,  g_e2);
        cudaGetSymbolAddress((void**)&ph0,  g_h0);
        cudaGetSymbolAddress((void**)&ph1,  g_h1);
        cudaGetSymbolAddress((void**)&pup,  g_up);
        cudaGetSymbolAddress((void**)&pw2,  g_wp2);
        cudaGetSymbolAddress((void**)&pw3,  g_wp3);
        cudaGetSymbolAddress((void**)&pwul, g_wpul);
        cudaGetSymbolAddress((void**)&pwh0, g_wph0);
        cudaGetSymbolAddress((void**)&pwh1, g_wph1);
        cudaFuncSetAttribute(convmma_k<32, false, 0, true>,
                             cudaFuncAttributeMaxDynamicSharedMemorySize, SM32B);
        cudaFuncSetAttribute(convmma_k<64, false, 0, false>,
                             cudaFuncAttributeMaxDynamicSharedMemorySize, SM64B);
        cudaFuncSetAttribute(convmma_k<64, true, 1, false>,
                             cudaFuncAttributeMaxDynamicSharedMemorySize, SM64B);
        cudaFuncSetAttribute(convmma_k<64, true, 2, false>,
                             cudaFuncAttributeMaxDynamicSharedMemorySize, SM64B);
    }
    const size_t HSZ = 36ull * 64 * PIX;

    zero_init_k<<<9216, 256>>>();
    prep_w_k<<<dim3(144, 5), 256>>>(w2, w3, wul, wh0, wh1);

    // encoder for all (t,b) up front
    conv1_k<<<dim3(16, 32), 256>>>(u, w1, g1, b1, pe1);
    convmma_k<32, false, 0, true ><<<dim3(16, 32), 256, SM32B>>>(
        pe1, pw2, g2, b2, nullptr, pe2, nullptr, 0);
    convmma_k<64, false, 0, false><<<dim3(16, 32), 256, SM64B>>>(
        pe2, pw3, g3, b3, nullptr, px, nullptr, 0);

    // recurrent steps
    for (int t = 0; t < 8; t++) {
        int rp = t & 1, wp = 1 - rp;
        // h0 = tanh(x_t + circ-shift conv(h0_old, w_h0))
        convmma_k<64, true, 1, false><<<dim3(16, 36), 256, SM64B>>>(
            ph0 + rp * HSZ, pwh0, nullptr, nullptr, px, ph0 + wp * HSZ, nullptr, t);
        // up = relu(bn(conv(h0_new, w_ul)))  (zero pad, fp32 addend out)
        convmma_k<64, false, 0, false><<<dim3(16, 36), 256, SM64B>>>(
            ph0 + wp * HSZ, pwul, gul, bul, nullptr, pup, nullptr, 0);
        // h1 = tanh(up + circ-shift conv(h1_old, w_h1)); fused d_out store
        convmma_k<64, true, 2, false><<<dim3(16, 36), 256, SM64B>>>(
            ph1 + rp * HSZ, pwh1, nullptr, nullptr, pup, ph1 + wp * HSZ, out, t);
    }
}